// round 4
// baseline (speedup 1.0000x reference)
#include <cuda_runtime.h>

// ---------------- problem constants (fixed shapes per reference) ----------------
#define Bq 2
#define Hq 16
#define Sq 4096
#define DK 128
#define DV 256
#define LC 64
#define NCHUNK (Sq / LC)        // 64
#define BHN (Bq * Hq)           // 32
#define NCG (BHN * NCHUNK)      // 2048
#define NROWS (BHN * Sq)        // 131072
#define QSCALE 0.08838834764831845f   // 128^-0.5
#define EPSN 1e-6f
#define OUT_ELEMS ((size_t)NROWS * DV)          // 33,554,432
#define ST_ELEMS  ((size_t)BHN * DK * DV)       // 1,048,576

// ---------------- scratch (static device globals; allocation-free) ----------------
__device__ float g_qs[(size_t)NROWS * DK];   // normalized q * exp(gcum) * SCALE
__device__ float g_kg[(size_t)NROWS * DK];   // normalized k * exp(gcum)
__device__ float g_W [(size_t)NROWS * DK];   // T @ k_gated
__device__ float g_T [(size_t)NCG * LC * LC];   // row-major
__device__ float g_Aq[(size_t)NCG * LC * LC];   // TRANSPOSED: [col][row]
__device__ float g_gexp[(size_t)NROWS];
__device__ float g_decay[NCG];

// ---------------- stage 1 ----------------
#define QK_STR 132   // 128 + 4 pad
#define TT_STR 68    // 64 + 4 pad

extern "C" __global__ void __launch_bounds__(256, 2)
gdn_stage1(const float* __restrict__ q, const float* __restrict__ k,
           const float* __restrict__ g, const float* __restrict__ beta)
{
    extern __shared__ float sh[];
    float* sq   = sh;                        // LC * QK_STR
    float* sk   = sq + LC * QK_STR;          // LC * QK_STR
    float* sA   = sk + LC * QK_STR;          // LC * TT_STR
    float* sT   = sA + LC * TT_STR;          // LC * TT_STR
    float* gcum = sT + LC * TT_STR;          // LC
    float* gexp = gcum + LC;                 // LC
    float* bta  = gexp + LC;                 // LC
    float* sh_tot = bta + LC;                // 1

    const int cg   = blockIdx.x;
    const int bh   = cg / NCHUNK;
    const int cc   = cg % NCHUNK;
    const int row0 = bh * Sq + cc * LC;
    const int tid  = threadIdx.x;

    // ---- gate cumsum via warp scan (warps 0,1), beta load ----
    if (tid < LC) bta[tid] = beta[row0 + tid];
    float val = 0.f;
    if (tid < 64) {
        val = g[row0 + tid];
#pragma unroll
        for (int off = 1; off < 32; off <<= 1) {
            float n = __shfl_up_sync(0xffffffffu, val, off);
            if ((tid & 31) >= off) val += n;
        }
    }
    if (tid == 31) sh_tot[0] = val;
    __syncthreads();
    if (tid >= 32 && tid < 64) val += sh_tot[0];
    if (tid < 64) {
        gcum[tid] = val;
        const float e = expf(val);
        gexp[tid] = e;
        if (tid == 63) g_decay[cg] = e;
    }
    __syncthreads();

    // ---- load + L2-normalize q,k (4 threads per row) ----
    {
        const int r = tid >> 2, lane = tid & 3;
        const float4* qr = (const float4*)(q + (size_t)(row0 + r) * DK) + lane * 8;
        const float4* kr = (const float4*)(k + (size_t)(row0 + r) * DK) + lane * 8;
        float4 qv[8], kv[8];
        float sq2 = 0.f, sk2 = 0.f;
#pragma unroll
        for (int u = 0; u < 8; u++) {
            qv[u] = qr[u]; kv[u] = kr[u];
            sq2 += qv[u].x*qv[u].x + qv[u].y*qv[u].y + qv[u].z*qv[u].z + qv[u].w*qv[u].w;
            sk2 += kv[u].x*kv[u].x + kv[u].y*kv[u].y + kv[u].z*kv[u].z + kv[u].w*kv[u].w;
        }
        sq2 += __shfl_xor_sync(0xffffffffu, sq2, 1);
        sq2 += __shfl_xor_sync(0xffffffffu, sq2, 2);
        sk2 += __shfl_xor_sync(0xffffffffu, sk2, 1);
        sk2 += __shfl_xor_sync(0xffffffffu, sk2, 2);
        const float qi = 1.f / (sqrtf(sq2) + EPSN);
        const float ki = 1.f / (sqrtf(sk2) + EPSN);
        float4* dq = (float4*)(sq + r * QK_STR + lane * 32);
        float4* dk = (float4*)(sk + r * QK_STR + lane * 32);
#pragma unroll
        for (int u = 0; u < 8; u++) {
            float4 a = qv[u]; a.x *= qi; a.y *= qi; a.z *= qi; a.w *= qi; dq[u] = a;
            float4 b = kv[u]; b.x *= ki; b.y *= ki; b.z *= ki; b.w *= ki; dk[u] = b;
        }
    }
    __syncthreads();

    // ---- fused register-blocked GEMM: KK = k@k^T, QK = q@k^T (full 64x64 each)
    // thread handles rows {tr, tr+16, tr+32, tr+48} x cols {tc, tc+16, tc+32, tc+48}
    {
        const int tr = tid & 15;
        const int tc = tid >> 4;
        float kk[16], qk[16];
#pragma unroll
        for (int i = 0; i < 16; i++) { kk[i] = 0.f; qk[i] = 0.f; }

#pragma unroll 4
        for (int m = 0; m < DK; m += 4) {
            float4 bv[4], av[4], qv[4];
#pragma unroll
            for (int c = 0; c < 4; c++)
                bv[c] = *(const float4*)(sk + (tc + 16 * c) * QK_STR + m);
#pragma unroll
            for (int r = 0; r < 4; r++) {
                av[r] = *(const float4*)(sk + (tr + 16 * r) * QK_STR + m);
                qv[r] = *(const float4*)(sq + (tr + 16 * r) * QK_STR + m);
            }
#pragma unroll
            for (int r = 0; r < 4; r++)
#pragma unroll
                for (int c = 0; c < 4; c++) {
                    kk[r*4+c] += av[r].x*bv[c].x + av[r].y*bv[c].y
                               + av[r].z*bv[c].z + av[r].w*bv[c].w;
                    qk[r*4+c] += qv[r].x*bv[c].x + qv[r].y*bv[c].y
                               + qv[r].z*bv[c].z + qv[r].w*bv[c].w;
                }
        }

        // epilogue: gate + mask; sA (row-major), sT zero, AqT (transposed) to gmem
        float inv_ge[4], btr[4];
#pragma unroll
        for (int r = 0; r < 4; r++) {
            inv_ge[r] = 1.f / gexp[tr + 16 * r];
            btr[r]    = bta[tr + 16 * r];
        }
        float* Aqg = g_Aq + (size_t)cg * (LC * LC);
#pragma unroll
        for (int r = 0; r < 4; r++) {
            const int row = tr + 16 * r;
#pragma unroll
            for (int c = 0; c < 4; c++) {
                const int col = tc + 16 * c;
                const float gate = gexp[col] * inv_ge[r];
                sA[row * TT_STR + col] = (col < row) ? btr[r] * kk[r*4+c] * gate : 0.f;
                sT[row * TT_STR + col] = 0.f;
                Aqg[col * LC + row] = (col <= row) ? QSCALE * qk[r*4+c] * gate : 0.f;
            }
        }
    }
    __syncthreads();

    // ---- threads 0..63: forward substitution T = A^-1 diag(beta)
    // ---- threads 64..191: scale rows (qs, kg) concurrently
    if (tid < LC) {
        const int j = tid;
        sT[j * TT_STR + j] = bta[j];
        for (int i = j + 1; i < LC; i++) {
            float s = 0.f;
            for (int m = j; m < i; m++) s -= sA[i * TT_STR + m] * sT[m * TT_STR + j];
            sT[i * TT_STR + j] = s;
        }
    } else if (tid < 192) {
        const int t = tid - 64;
        const int r = t >> 1, half = t & 1;
        const float ge = gexp[r];
        const float qf = ge * QSCALE;
        float4* pq = (float4*)(sq + r * QK_STR + half * 64);
        float4* pk = (float4*)(sk + r * QK_STR + half * 64);
        float4* oq = (float4*)(g_qs + (size_t)(row0 + r) * DK + half * 64);
        float4* ok = (float4*)(g_kg + (size_t)(row0 + r) * DK + half * 64);
#pragma unroll
        for (int u = 0; u < 16; u++) {
            float4 a = pq[u]; a.x *= qf; a.y *= qf; a.z *= qf; a.w *= qf; oq[u] = a;
            float4 b = pk[u]; b.x *= ge; b.y *= ge; b.z *= ge; b.w *= ge; pk[u] = b; ok[u] = b;
        }
        if (half == 0) g_gexp[row0 + r] = ge;
    }
    __syncthreads();

    // ---- write T to global (row-major)
    for (int i4 = tid; i4 < LC * LC / 4; i4 += 256) {
        const int i = i4 >> 4, j4 = i4 & 15;
        *(float4*)(g_T + (size_t)cg * (LC * LC) + i * LC + j4 * 4) =
            *(const float4*)(sT + i * TT_STR + j4 * 4);
    }

    // ---- W = T @ k_gated  (64x64 * 64x128)
    {
        const int colg = tid & 31;       // 4-col group
        const int rowg = tid >> 5;       // 0..7 ; rows rowg + 8u
        float4 acc[8];
#pragma unroll
        for (int u = 0; u < 8; u++) acc[u] = make_float4(0.f, 0.f, 0.f, 0.f);
        for (int m = 0; m < LC; m++) {
            const float4 b = *(const float4*)(sk + m * QK_STR + colg * 4);
#pragma unroll
            for (int u = 0; u < 8; u++) {
                const float a = sT[(rowg + 8 * u) * TT_STR + m];
                acc[u].x += a * b.x; acc[u].y += a * b.y;
                acc[u].z += a * b.z; acc[u].w += a * b.w;
            }
        }
#pragma unroll
        for (int u = 0; u < 8; u++)
            *(float4*)(g_W + (size_t)(row0 + rowg + 8 * u) * DK + colg * 4) = acc[u];
    }
}

// ---------------- stage 2 : sequential scan over chunks (512 threads) ----------------
#define VT 32
#define NT (DV / VT)   // 8
#define SSTR 36
#define CSTR 36
#define ASTR 68
#define BSTR 132
#define TPB2 512

extern "C" __global__ void __launch_bounds__(TPB2, 2)
gdn_stage2(const float* __restrict__ v, float* __restrict__ out, const int write_state)
{
    extern __shared__ float sh[];
    float* sS  = sh;                   // DK * SSTR  (state tile, 128 x 32)
    float* sC  = sS + DK * SSTR;       // LC * CSTR  (correction, 64 x 32)
    float* sV  = sC + LC * CSTR;       // LC * CSTR  (v_gated tile)
    float* sbA = sV + LC * CSTR;       // LC * ASTR  (T / AqT staging)
    float* sbB = sbA + LC * ASTR;      // LC * BSTR  (W / qs / kg staging)

    const int bx   = blockIdx.x;
    const int bh   = bx / NT;
    const int tile = bx % NT;
    const int tid  = threadIdx.x;
    const int colg = tid & 7;          // 4-col group within the 32-col tile
    const int row  = tid >> 3;         // 0..63
    const int c4   = colg * 4;
    const int vcol0 = tile * VT;
    const int rA = row * ASTR;
    const int rB = row * BSTR;

    for (int idx = tid; idx < DK * VT; idx += TPB2)
        sS[(idx >> 5) * SSTR + (idx & 31)] = 0.f;
    __syncthreads();

    for (int cc = 0; cc < NCHUNK; cc++) {
        const int cg   = bh * NCHUNK + cc;
        const int row0 = bh * Sq + cc * LC;
        const float* Tg  = g_T  + (size_t)cg * (LC * LC);
        const float* Aqg = g_Aq + (size_t)cg * (LC * LC);

        // ---- stage T -> sbA, W -> sbB, v*gexp -> sV
        for (int i4 = tid; i4 < LC * LC / 4; i4 += TPB2) {
            const int i = i4 >> 4, j4 = i4 & 15;
            *(float4*)(sbA + i * ASTR + j4 * 4) = *(const float4*)(Tg + i * LC + j4 * 4);
        }
        for (int i4 = tid; i4 < LC * DK / 4; i4 += TPB2) {
            const int i = i4 >> 5, j4 = i4 & 31;
            *(float4*)(sbB + i * BSTR + j4 * 4) =
                *(const float4*)(g_W + (size_t)(row0 + i) * DK + j4 * 4);
        }
        {
            const int i = tid >> 3, j4 = tid & 7;   // exactly 512 float4s
            const float ge = g_gexp[row0 + i];
            float4 vv = *(const float4*)(v + (size_t)(row0 + i) * DV + vcol0 + j4 * 4);
            vv.x *= ge; vv.y *= ge; vv.z *= ge; vv.w *= ge;
            *(float4*)(sV + i * CSTR + j4 * 4) = vv;
        }
        __syncthreads();

        // ---- corr = T @ Vg  -  W @ S   (row `row`, 4 cols)
        float4 u = make_float4(0.f, 0.f, 0.f, 0.f);
#pragma unroll 16
        for (int m = 0; m < LC; m++) {
            const float4 b = *(const float4*)(sV + m * CSTR + c4);
            const float a = sbA[rA + m];
            u.x += a*b.x; u.y += a*b.y; u.z += a*b.z; u.w += a*b.w;
        }
#pragma unroll 16
        for (int m = 0; m < DK; m++) {
            const float4 b = *(const float4*)(sS + m * SSTR + c4);
            const float a = sbB[rB + m];
            u.x -= a*b.x; u.y -= a*b.y; u.z -= a*b.z; u.w -= a*b.w;
        }
        *(float4*)(sC + row * CSTR + c4) = u;
        __syncthreads();

        // ---- stage AqT -> sbA (transposed layout), qs -> sbB
        for (int i4 = tid; i4 < LC * LC / 4; i4 += TPB2) {
            const int i = i4 >> 4, j4 = i4 & 15;
            *(float4*)(sbA + i * ASTR + j4 * 4) = *(const float4*)(Aqg + i * LC + j4 * 4);
        }
        for (int i4 = tid; i4 < LC * DK / 4; i4 += TPB2) {
            const int i = i4 >> 5, j4 = i4 & 31;
            *(float4*)(sbB + i * BSTR + j4 * 4) =
                *(const float4*)(g_qs + (size_t)(row0 + i) * DK + j4 * 4);
        }
        __syncthreads();

        // ---- O = qs @ S + Aq @ corr   (Aq accessed transposed: sbA[m][row])
        float4 o = make_float4(0.f, 0.f, 0.f, 0.f);
#pragma unroll 16
        for (int m = 0; m < DK; m++) {
            const float4 b = *(const float4*)(sS + m * SSTR + c4);
            const float a = sbB[rB + m];
            o.x += a*b.x; o.y += a*b.y; o.z += a*b.z; o.w += a*b.w;
        }
#pragma unroll 16
        for (int m = 0; m < LC; m++) {
            const float4 b = *(const float4*)(sC + m * CSTR + c4);
            const float a = sbA[m * ASTR + row];
            o.x += a*b.x; o.y += a*b.y; o.z += a*b.z; o.w += a*b.w;
        }
        *(float4*)(out + (size_t)(row0 + row) * DV + vcol0 + c4) = o;
        __syncthreads();

        // ---- stage kg -> sbB
        for (int i4 = tid; i4 < LC * DK / 4; i4 += TPB2) {
            const int i = i4 >> 5, j4 = i4 & 31;
            *(float4*)(sbB + i * BSTR + j4 * 4) =
                *(const float4*)(g_kg + (size_t)(row0 + i) * DK + j4 * 4);
        }
        __syncthreads();

        // ---- S = decay*S + kg^T @ corr   (rows row, row+64 of 128)
        float4 s0 = make_float4(0.f,0.f,0.f,0.f), s1 = s0;
#pragma unroll 16
        for (int i = 0; i < LC; i++) {
            const float4 b = *(const float4*)(sC + i * CSTR + c4);
            const float k0 = sbB[i * BSTR + row];
            const float k1 = sbB[i * BSTR + row + 64];
            s0.x += k0*b.x; s0.y += k0*b.y; s0.z += k0*b.z; s0.w += k0*b.w;
            s1.x += k1*b.x; s1.y += k1*b.y; s1.z += k1*b.z; s1.w += k1*b.w;
        }
        const float dec = g_decay[cg];
        {
            float4* p; float4 cur;
            p = (float4*)(sS + row * SSTR + c4);          cur = *p;
            cur.x = cur.x*dec + s0.x; cur.y = cur.y*dec + s0.y;
            cur.z = cur.z*dec + s0.z; cur.w = cur.w*dec + s0.w; *p = cur;
            p = (float4*)(sS + (row + 64) * SSTR + c4);   cur = *p;
            cur.x = cur.x*dec + s1.x; cur.y = cur.y*dec + s1.y;
            cur.z = cur.z*dec + s1.z; cur.w = cur.w*dec + s1.w; *p = cur;
        }
        __syncthreads();
    }

    if (write_state) {
        for (int idx = tid; idx < DK * VT; idx += TPB2) {
            const int d = idx >> 5, ccl = idx & 31;
            out[OUT_ELEMS + ((size_t)bh * DK + d) * DV + vcol0 + ccl] = sS[d * SSTR + ccl];
        }
    }
}

// ---------------- launch ----------------
extern "C" void kernel_launch(void* const* d_in, const int* in_sizes, int n_in,
                              void* d_out, int out_size)
{
    const float* q    = (const float*)d_in[0];
    const float* k    = (const float*)d_in[1];
    const float* v    = (const float*)d_in[2];
    const float* g    = (const float*)d_in[3];
    const float* beta = (const float*)d_in[4];
    float* out = (float*)d_out;

    const int write_state = ((size_t)out_size >= OUT_ELEMS + ST_ELEMS) ? 1 : 0;

    const int s1_smem = (int)((2 * LC * QK_STR + 2 * LC * TT_STR + 3 * LC + 4) * sizeof(float));
    const int s2_smem = (int)((DK * SSTR + 2 * LC * CSTR + LC * ASTR + LC * BSTR) * sizeof(float));

    cudaFuncSetAttribute((const void*)gdn_stage1,
                         cudaFuncAttributeMaxDynamicSharedMemorySize, s1_smem);
    cudaFuncSetAttribute((const void*)gdn_stage2,
                         cudaFuncAttributeMaxDynamicSharedMemorySize, s2_smem);

    gdn_stage1<<<NCG, 256, s1_smem>>>(q, k, g, beta);
    gdn_stage2<<<BHN * NT, TPB2, s2_smem>>>(v, out, write_state);
}

// round 5
// speedup vs baseline: 1.8285x; 1.8285x over previous
#include <cuda_runtime.h>

// ---------------- problem constants ----------------
#define Bq 2
#define Hq 16
#define Sq 4096
#define DK 128
#define DV 256
#define LC 64
#define NCHUNK (Sq / LC)        // 64
#define BHN (Bq * Hq)           // 32
#define NCG (BHN * NCHUNK)      // 2048
#define NROWS (BHN * Sq)        // 131072
#define QSCALE 0.08838834764831845f
#define EPSN 1e-6f
#define OUT_ELEMS ((size_t)NROWS * DV)
#define ST_ELEMS  ((size_t)BHN * DK * DV)

// ---------------- scratch ----------------
// per-chunk contiguous blocks; A-operands stored TRANSPOSED [m][row]
__device__ float g_Tt [(size_t)NCG * LC * LC];   // T^T  [m][i]
__device__ float g_Aqt[(size_t)NCG * LC * LC];   // Aq^T [m][i]
__device__ float g_Wt [(size_t)NCG * DK * LC];   // W^T  [dk][i]
__device__ float g_Qt [(size_t)NCG * DK * LC];   // qs^T [dk][i]
__device__ float g_Kg [(size_t)NCG * LC * DK];   // kg   [i][dk]
__device__ float g_gexp[(size_t)NROWS];
__device__ float g_decay[NCG];

// ---------------- f32x2 helpers ----------------
__device__ __forceinline__ unsigned long long pk2(float x, float y) {
    unsigned long long r;
    asm("mov.b64 %0, {%1, %2};" : "=l"(r) : "f"(x), "f"(y));
    return r;
}
__device__ __forceinline__ void fma2(unsigned long long& d,
                                     unsigned long long a, unsigned long long b) {
    asm("fma.rn.f32x2 %0, %1, %2, %3;" : "=l"(d) : "l"(a), "l"(b), "l"(d));
}
union U2 { unsigned long long u; float2 f; };

// ---------------- stage 1 ----------------
#define QK_STR 132
#define TT_STR 68

extern "C" __global__ void __launch_bounds__(256, 2)
gdn_stage1(const float* __restrict__ q, const float* __restrict__ k,
           const float* __restrict__ g, const float* __restrict__ beta)
{
    extern __shared__ float sh[];
    float* sq   = sh;                        // LC * QK_STR
    float* sk   = sq + LC * QK_STR;          // LC * QK_STR
    float* sA   = sk + LC * QK_STR;          // LC * TT_STR
    float* sTt  = sA + LC * TT_STR;          // LC * TT_STR (T^T: [j][i])
    float* gcum = sTt + LC * TT_STR;         // LC
    float* gexp = gcum + LC;                 // LC
    float* bta  = gexp + LC;                 // LC
    float* sh_tot = bta + LC;                // 1

    const int cg   = blockIdx.x;
    const int bh   = cg / NCHUNK;
    const int cc   = cg % NCHUNK;
    const int row0 = bh * Sq + cc * LC;
    const int tid  = threadIdx.x;

    // gate cumsum via warp scan
    if (tid < LC) bta[tid] = beta[row0 + tid];
    float val = 0.f;
    if (tid < 64) {
        val = g[row0 + tid];
#pragma unroll
        for (int off = 1; off < 32; off <<= 1) {
            float n = __shfl_up_sync(0xffffffffu, val, off);
            if ((tid & 31) >= off) val += n;
        }
    }
    if (tid == 31) sh_tot[0] = val;
    __syncthreads();
    if (tid >= 32 && tid < 64) val += sh_tot[0];
    if (tid < 64) {
        gcum[tid] = val;
        const float e = expf(val);
        gexp[tid] = e;
        if (tid == 63) g_decay[cg] = e;
    }
    __syncthreads();

    // load + L2-normalize q,k
    {
        const int r = tid >> 2, lane = tid & 3;
        const float4* qr = (const float4*)(q + (size_t)(row0 + r) * DK) + lane * 8;
        const float4* kr = (const float4*)(k + (size_t)(row0 + r) * DK) + lane * 8;
        float4 qv[8], kv[8];
        float sq2 = 0.f, sk2 = 0.f;
#pragma unroll
        for (int u = 0; u < 8; u++) {
            qv[u] = qr[u]; kv[u] = kr[u];
            sq2 += qv[u].x*qv[u].x + qv[u].y*qv[u].y + qv[u].z*qv[u].z + qv[u].w*qv[u].w;
            sk2 += kv[u].x*kv[u].x + kv[u].y*kv[u].y + kv[u].z*kv[u].z + kv[u].w*kv[u].w;
        }
        sq2 += __shfl_xor_sync(0xffffffffu, sq2, 1);
        sq2 += __shfl_xor_sync(0xffffffffu, sq2, 2);
        sk2 += __shfl_xor_sync(0xffffffffu, sk2, 1);
        sk2 += __shfl_xor_sync(0xffffffffu, sk2, 2);
        const float qi = 1.f / (sqrtf(sq2) + EPSN);
        const float ki = 1.f / (sqrtf(sk2) + EPSN);
        float4* dq = (float4*)(sq + r * QK_STR + lane * 32);
        float4* dk = (float4*)(sk + r * QK_STR + lane * 32);
#pragma unroll
        for (int u = 0; u < 8; u++) {
            float4 a = qv[u]; a.x *= qi; a.y *= qi; a.z *= qi; a.w *= qi; dq[u] = a;
            float4 b = kv[u]; b.x *= ki; b.y *= ki; b.z *= ki; b.w *= ki; dk[u] = b;
        }
    }
    __syncthreads();

    // fused GEMM: KK = k@k^T, QK = q@k^T (64x64 each), 4x4 per thread
    {
        const int tr = tid & 15;
        const int tc = tid >> 4;
        float kk[16], qk[16];
#pragma unroll
        for (int i = 0; i < 16; i++) { kk[i] = 0.f; qk[i] = 0.f; }

#pragma unroll 4
        for (int m = 0; m < DK; m += 4) {
            float4 bv[4], av[4], qv[4];
#pragma unroll
            for (int c = 0; c < 4; c++)
                bv[c] = *(const float4*)(sk + (tc + 16 * c) * QK_STR + m);
#pragma unroll
            for (int r = 0; r < 4; r++) {
                av[r] = *(const float4*)(sk + (tr + 16 * r) * QK_STR + m);
                qv[r] = *(const float4*)(sq + (tr + 16 * r) * QK_STR + m);
            }
#pragma unroll
            for (int r = 0; r < 4; r++)
#pragma unroll
                for (int c = 0; c < 4; c++) {
                    kk[r*4+c] += av[r].x*bv[c].x + av[r].y*bv[c].y
                               + av[r].z*bv[c].z + av[r].w*bv[c].w;
                    qk[r*4+c] += qv[r].x*bv[c].x + qv[r].y*bv[c].y
                               + qv[r].z*bv[c].z + qv[r].w*bv[c].w;
                }
        }

        // epilogue: sA row-major, sTt zero, Aq^T to gmem
        float inv_ge[4], btr[4];
#pragma unroll
        for (int r = 0; r < 4; r++) {
            inv_ge[r] = 1.f / gexp[tr + 16 * r];
            btr[r]    = bta[tr + 16 * r];
        }
        float* Aqg = g_Aqt + (size_t)cg * (LC * LC);
#pragma unroll
        for (int r = 0; r < 4; r++) {
            const int row = tr + 16 * r;
#pragma unroll
            for (int c = 0; c < 4; c++) {
                const int col = tc + 16 * c;
                const float gate = gexp[col] * inv_ge[r];
                sA[row * TT_STR + col] = (col < row) ? btr[r] * kk[r*4+c] * gate : 0.f;
                sTt[row * TT_STR + col] = 0.f;
                Aqg[col * LC + row] = (col <= row) ? QSCALE * qk[r*4+c] * gate : 0.f;
            }
        }
    }
    __syncthreads();

    // threads 0..63: forward substitution into T^T (thread j writes row j of T^T)
    // threads 64..191: scale q,k rows in place
    if (tid < LC) {
        const int j = tid;
        sTt[j * TT_STR + j] = bta[j];
        for (int i = j + 1; i < LC; i++) {
            float s = 0.f;
            for (int m = j; m < i; m++) s -= sA[i * TT_STR + m] * sTt[j * TT_STR + m];
            sTt[j * TT_STR + i] = s;
        }
    } else if (tid < 192) {
        const int t = tid - 64;
        const int r = t >> 1, half = t & 1;
        const float ge = gexp[r];
        const float qf = ge * QSCALE;
        float4* pq = (float4*)(sq + r * QK_STR + half * 64);
        float4* pk = (float4*)(sk + r * QK_STR + half * 64);
#pragma unroll
        for (int u = 0; u < 16; u++) {
            float4 a = pq[u]; a.x *= qf; a.y *= qf; a.z *= qf; a.w *= qf; pq[u] = a;
            float4 b = pk[u]; b.x *= ge; b.y *= ge; b.z *= ge; b.w *= ge; pk[u] = b;
        }
        if (half == 0) g_gexp[row0 + r] = ge;
    }
    __syncthreads();

    // write T^T to global: [m][i]
    {
        float* Tg = g_Tt + (size_t)cg * (LC * LC);
        for (int i4 = tid; i4 < LC * LC / 4; i4 += 256) {
            const int m = i4 >> 4, j4 = i4 & 15;
            *(float4*)(Tg + m * LC + j4 * 4) = *(const float4*)(sTt + m * TT_STR + j4 * 4);
        }
    }

    // W^T = (T @ kg)^T : thread computes 4 i x 8 dk, stores per-dk rows
    {
        const int i0  = (tid & 15) * 4;
        const int dk0 = (tid >> 4) * 8;
        float4 acc[8];
#pragma unroll
        for (int d = 0; d < 8; d++) acc[d] = make_float4(0.f, 0.f, 0.f, 0.f);
#pragma unroll 4
        for (int m = 0; m < LC; m++) {
            const float4 a  = *(const float4*)(sTt + m * TT_STR + i0);
            const float4 b0 = *(const float4*)(sk + m * QK_STR + dk0);
            const float4 b1 = *(const float4*)(sk + m * QK_STR + dk0 + 4);
            float bs[8] = {b0.x, b0.y, b0.z, b0.w, b1.x, b1.y, b1.z, b1.w};
#pragma unroll
            for (int d = 0; d < 8; d++) {
                acc[d].x += a.x * bs[d]; acc[d].y += a.y * bs[d];
                acc[d].z += a.z * bs[d]; acc[d].w += a.w * bs[d];
            }
        }
        float* Wg = g_Wt + (size_t)cg * (DK * LC);
#pragma unroll
        for (int d = 0; d < 8; d++)
            *(float4*)(Wg + (dk0 + d) * LC + i0) = acc[d];
    }

    // qs^T: [dk][i] via shared transpose
    {
        float* Qg = g_Qt + (size_t)cg * (DK * LC);
        for (int idx = tid; idx < DK * 16; idx += 256) {
            const int dk = idx >> 4, i0 = (idx & 15) * 4;
            float4 vv;
            vv.x = sq[(i0 + 0) * QK_STR + dk];
            vv.y = sq[(i0 + 1) * QK_STR + dk];
            vv.z = sq[(i0 + 2) * QK_STR + dk];
            vv.w = sq[(i0 + 3) * QK_STR + dk];
            *(float4*)(Qg + dk * LC + i0) = vv;
        }
    }

    // kg row-major: [i][dk]
    {
        float* Kg = g_Kg + (size_t)cg * (LC * DK);
        for (int i4 = tid; i4 < LC * DK / 4; i4 += 256) {
            const int i = i4 >> 5, j4 = i4 & 31;
            *(float4*)(Kg + i * DK + j4 * 4) = *(const float4*)(sk + i * QK_STR + j4 * 4);
        }
    }
}

// ---------------- stage 2 : scan, VT=64, f32x2 register-blocked ----------------
#define VT 64
#define NT (DV / VT)   // 4
#define S2STR 68       // 64-col tiles stride
#define KGSTR 132
#define TPB2 256

extern "C" __global__ void __launch_bounds__(TPB2, 1)
gdn_stage2(const float* __restrict__ v, float* __restrict__ out, const int write_state)
{
    extern __shared__ float sh[];
    float* sS  = sh;                     // 128 * 68
    float* sC  = sS  + DK * S2STR;       // 64 * 68
    float* sV  = sC  + LC * S2STR;       // 64 * 68
    float* sT  = sV  + LC * S2STR;       // 64 * 68   (T^T)
    float* sAq = sT  + LC * S2STR;       // 64 * 68   (Aq^T)
    float* sW  = sAq + LC * S2STR;       // 128 * 68  (W^T)
    float* sQ  = sW  + DK * S2STR;       // 128 * 68  (qs^T)
    float* sKg = sQ  + DK * S2STR;       // 64 * 132  (kg)

    const int bx   = blockIdx.x;
    const int bh   = bx / NT;
    const int tile = bx % NT;
    const int tid  = threadIdx.x;
    const int c0   = (tid & 15) * 4;     // 4 cols
    const int r0   = (tid >> 4) * 4;     // 4 consecutive rows (corr/O)
    const int r0s  = (tid >> 4) * 8;     // 8 consecutive rows (S-update)
    const int vcol0 = tile * VT;

    for (int idx = tid; idx < DK * 16; idx += TPB2)
        *(float4*)(sS + (idx >> 4) * S2STR + (idx & 15) * 4) =
            make_float4(0.f, 0.f, 0.f, 0.f);
    __syncthreads();

    for (int cc = 0; cc < NCHUNK; cc++) {
        const int cg   = bh * NCHUNK + cc;
        const int row0 = bh * Sq + cc * LC;
        const float* Tg  = g_Tt  + (size_t)cg * (LC * LC);
        const float* Aqg = g_Aqt + (size_t)cg * (LC * LC);
        const float* Wg  = g_Wt  + (size_t)cg * (DK * LC);
        const float* Qg  = g_Qt  + (size_t)cg * (DK * LC);
        const float* Kgg = g_Kg  + (size_t)cg * (LC * DK);

        // ---- stage ALL operands for this chunk
        for (int i4 = tid; i4 < LC * 16; i4 += TPB2) {       // T^T, Aq^T
            const int m = i4 >> 4, j4 = (i4 & 15) * 4;
            *(float4*)(sT  + m * S2STR + j4) = *(const float4*)(Tg  + m * LC + j4);
            *(float4*)(sAq + m * S2STR + j4) = *(const float4*)(Aqg + m * LC + j4);
        }
        for (int i4 = tid; i4 < DK * 16; i4 += TPB2) {       // W^T, qs^T
            const int m = i4 >> 4, j4 = (i4 & 15) * 4;
            *(float4*)(sW + m * S2STR + j4) = *(const float4*)(Wg + m * LC + j4);
            *(float4*)(sQ + m * S2STR + j4) = *(const float4*)(Qg + m * LC + j4);
        }
        for (int i4 = tid; i4 < LC * 32; i4 += TPB2) {       // kg
            const int i = i4 >> 5, j4 = (i4 & 31) * 4;
            *(float4*)(sKg + i * KGSTR + j4) = *(const float4*)(Kgg + i * DK + j4);
        }
        for (int i4 = tid; i4 < LC * 16; i4 += TPB2) {       // v * gexp
            const int i = i4 >> 4, j4 = (i4 & 15) * 4;
            const float ge = g_gexp[row0 + i];
            float4 vv = *(const float4*)(v + (size_t)(row0 + i) * DV + vcol0 + j4);
            vv.x *= ge; vv.y *= ge; vv.z *= ge; vv.w *= ge;
            *(float4*)(sV + i * S2STR + j4) = vv;
        }
        __syncthreads();

        // ---- corr = T @ Vg - W @ S
        {
            unsigned long long ap[4][2], an[4][2];
#pragma unroll
            for (int r = 0; r < 4; r++) { ap[r][0]=0ULL; ap[r][1]=0ULL; an[r][0]=0ULL; an[r][1]=0ULL; }
#pragma unroll 4
            for (int m = 0; m < LC; m++) {
                const float4 a = *(const float4*)(sT + m * S2STR + r0);
                const float4 b = *(const float4*)(sV + m * S2STR + c0);
                const unsigned long long b01 = pk2(b.x, b.y), b23 = pk2(b.z, b.w);
                unsigned long long aa;
                aa = pk2(a.x, a.x); fma2(ap[0][0], aa, b01); fma2(ap[0][1], aa, b23);
                aa = pk2(a.y, a.y); fma2(ap[1][0], aa, b01); fma2(ap[1][1], aa, b23);
                aa = pk2(a.z, a.z); fma2(ap[2][0], aa, b01); fma2(ap[2][1], aa, b23);
                aa = pk2(a.w, a.w); fma2(ap[3][0], aa, b01); fma2(ap[3][1], aa, b23);
            }
#pragma unroll 4
            for (int m = 0; m < DK; m++) {
                const float4 a = *(const float4*)(sW + m * S2STR + r0);
                const float4 b = *(const float4*)(sS + m * S2STR + c0);
                const unsigned long long b01 = pk2(b.x, b.y), b23 = pk2(b.z, b.w);
                unsigned long long aa;
                aa = pk2(a.x, a.x); fma2(an[0][0], aa, b01); fma2(an[0][1], aa, b23);
                aa = pk2(a.y, a.y); fma2(an[1][0], aa, b01); fma2(an[1][1], aa, b23);
                aa = pk2(a.z, a.z); fma2(an[2][0], aa, b01); fma2(an[2][1], aa, b23);
                aa = pk2(a.w, a.w); fma2(an[3][0], aa, b01); fma2(an[3][1], aa, b23);
            }
#pragma unroll
            for (int r = 0; r < 4; r++) {
                U2 p0, p1, n0, n1;
                p0.u = ap[r][0]; p1.u = ap[r][1]; n0.u = an[r][0]; n1.u = an[r][1];
                float4 res;
                res.x = p0.f.x - n0.f.x; res.y = p0.f.y - n0.f.y;
                res.z = p1.f.x - n1.f.x; res.w = p1.f.y - n1.f.y;
                *(float4*)(sC + (r0 + r) * S2STR + c0) = res;
            }
        }
        __syncthreads();

        // ---- O = qs @ S + Aq @ corr  -> gmem
        {
            unsigned long long ap[4][2], an[4][2];
#pragma unroll
            for (int r = 0; r < 4; r++) { ap[r][0]=0ULL; ap[r][1]=0ULL; an[r][0]=0ULL; an[r][1]=0ULL; }
#pragma unroll 4
            for (int m = 0; m < DK; m++) {
                const float4 a = *(const float4*)(sQ + m * S2STR + r0);
                const float4 b = *(const float4*)(sS + m * S2STR + c0);
                const unsigned long long b01 = pk2(b.x, b.y), b23 = pk2(b.z, b.w);
                unsigned long long aa;
                aa = pk2(a.x, a.x); fma2(ap[0][0], aa, b01); fma2(ap[0][1], aa, b23);
                aa = pk2(a.y, a.y); fma2(ap[1][0], aa, b01); fma2(ap[1][1], aa, b23);
                aa = pk2(a.z, a.z); fma2(ap[2][0], aa, b01); fma2(ap[2][1], aa, b23);
                aa = pk2(a.w, a.w); fma2(ap[3][0], aa, b01); fma2(ap[3][1], aa, b23);
            }
#pragma unroll 4
            for (int m = 0; m < LC; m++) {
                const float4 a = *(const float4*)(sAq + m * S2STR + r0);
                const float4 b = *(const float4*)(sC + m * S2STR + c0);
                const unsigned long long b01 = pk2(b.x, b.y), b23 = pk2(b.z, b.w);
                unsigned long long aa;
                aa = pk2(a.x, a.x); fma2(an[0][0], aa, b01); fma2(an[0][1], aa, b23);
                aa = pk2(a.y, a.y); fma2(an[1][0], aa, b01); fma2(an[1][1], aa, b23);
                aa = pk2(a.z, a.z); fma2(an[2][0], aa, b01); fma2(an[2][1], aa, b23);
                aa = pk2(a.w, a.w); fma2(an[3][0], aa, b01); fma2(an[3][1], aa, b23);
            }
#pragma unroll
            for (int r = 0; r < 4; r++) {
                U2 p0, p1, n0, n1;
                p0.u = ap[r][0]; p1.u = ap[r][1]; n0.u = an[r][0]; n1.u = an[r][1];
                float4 res;
                res.x = p0.f.x + n0.f.x; res.y = p0.f.y + n0.f.y;
                res.z = p1.f.x + n1.f.x; res.w = p1.f.y + n1.f.y;
                *(float4*)(out + (size_t)(row0 + r0 + r) * DV + vcol0 + c0) = res;
            }
        }
        __syncthreads();

        // ---- S = decay*S + kg^T @ corr   (8 dk rows x 4 cols per thread)
        {
            unsigned long long acc[8][2];
#pragma unroll
            for (int d = 0; d < 8; d++) { acc[d][0] = 0ULL; acc[d][1] = 0ULL; }
#pragma unroll 4
            for (int m = 0; m < LC; m++) {
                const float4 a0 = *(const float4*)(sKg + m * KGSTR + r0s);
                const float4 a1 = *(const float4*)(sKg + m * KGSTR + r0s + 4);
                const float4 b  = *(const float4*)(sC + m * S2STR + c0);
                const unsigned long long b01 = pk2(b.x, b.y), b23 = pk2(b.z, b.w);
                unsigned long long aa;
                aa = pk2(a0.x, a0.x); fma2(acc[0][0], aa, b01); fma2(acc[0][1], aa, b23);
                aa = pk2(a0.y, a0.y); fma2(acc[1][0], aa, b01); fma2(acc[1][1], aa, b23);
                aa = pk2(a0.z, a0.z); fma2(acc[2][0], aa, b01); fma2(acc[2][1], aa, b23);
                aa = pk2(a0.w, a0.w); fma2(acc[3][0], aa, b01); fma2(acc[3][1], aa, b23);
                aa = pk2(a1.x, a1.x); fma2(acc[4][0], aa, b01); fma2(acc[4][1], aa, b23);
                aa = pk2(a1.y, a1.y); fma2(acc[5][0], aa, b01); fma2(acc[5][1], aa, b23);
                aa = pk2(a1.z, a1.z); fma2(acc[6][0], aa, b01); fma2(acc[6][1], aa, b23);
                aa = pk2(a1.w, a1.w); fma2(acc[7][0], aa, b01); fma2(acc[7][1], aa, b23);
            }
            const float dec = g_decay[cg];
#pragma unroll
            for (int d = 0; d < 8; d++) {
                float4* p = (float4*)(sS + (r0s + d) * S2STR + c0);
                float4 cur = *p;
                U2 a0, a1; a0.u = acc[d][0]; a1.u = acc[d][1];
                cur.x = cur.x * dec + a0.f.x; cur.y = cur.y * dec + a0.f.y;
                cur.z = cur.z * dec + a1.f.x; cur.w = cur.w * dec + a1.f.y;
                *p = cur;
            }
        }
        __syncthreads();
    }

    if (write_state) {
        for (int idx = tid; idx < DK * 16; idx += TPB2) {
            const int d = idx >> 4, j4 = (idx & 15) * 4;
            *(float4*)(out + OUT_ELEMS + ((size_t)bh * DK + d) * DV + vcol0 + j4) =
                *(const float4*)(sS + d * S2STR + j4);
        }
    }
}

// ---------------- launch ----------------
extern "C" void kernel_launch(void* const* d_in, const int* in_sizes, int n_in,
                              void* d_out, int out_size)
{
    const float* q    = (const float*)d_in[0];
    const float* k    = (const float*)d_in[1];
    const float* v    = (const float*)d_in[2];
    const float* g    = (const float*)d_in[3];
    const float* beta = (const float*)d_in[4];
    float* out = (float*)d_out;

    const int write_state = ((size_t)out_size >= OUT_ELEMS + ST_ELEMS) ? 1 : 0;

    const int s1_smem = (int)((2 * LC * QK_STR + 2 * LC * TT_STR + 3 * LC + 4) * sizeof(float));
    const int s2_smem = (int)((DK * S2STR + 4 * LC * S2STR + 2 * DK * S2STR + LC * KGSTR)
                              * sizeof(float));   // 207,872 B

    cudaFuncSetAttribute((const void*)gdn_stage1,
                         cudaFuncAttributeMaxDynamicSharedMemorySize, s1_smem);
    cudaFuncSetAttribute((const void*)gdn_stage2,
                         cudaFuncAttributeMaxDynamicSharedMemorySize, s2_smem);

    gdn_stage1<<<NCG, 256, s1_smem>>>(q, k, g, beta);
    gdn_stage2<<<BHN * NT, TPB2, s2_smem>>>(v, out, write_state);
}